// round 4
// baseline (speedup 1.0000x reference)
#include <cuda_runtime.h>
#include <cstdint>

// Problem constants (shapes fixed by the dataset)
#define NN   100000      // nodes
#define EE   3200000     // edges (without self loops)
#define INC  128
#define HID  64
#define OUTC 16

// ---------------- scratch (static device globals; no allocation) -------------
__device__ float g_h0[NN * HID];      // x @ W1
__device__ float g_agg1[NN * HID];    // relu(aggregated layer-1 + b1)
__device__ float g_z[NN * 32];        // agg1 @ [W_mu | W_ls]
__device__ float g_dis[NN];           // (deg+1)^-1/2
__device__ int   g_src[EE];
__device__ int   g_dst[EE];
__device__ int   g_csr[EE];           // src indices sorted by dst
__device__ int   g_degi[NN];          // edge in-degree (without self loop)
__device__ int   g_offA[NN];          // block-local exclusive scan
__device__ int   g_off[NN];           // global exclusive scan (CSR row ptr)
__device__ int   g_woff[NN];          // scatter write cursors
__device__ int   g_bsum[1024];
__device__ int   g_bpre[1024];
__device__ int   g_is64;

// ---------------- dtype detection + index conversion + degree count ----------
__global__ void k_detect(const int* e) {
    int all_zero = 1;
    #pragma unroll
    for (int i = 1; i < 129; i += 2)
        if (e[i] != 0) { all_zero = 0; break; }
    g_is64 = all_zero;
}

__global__ void k_zero_deg(int n) {
    int i = blockIdx.x * blockDim.x + threadIdx.x;
    if (i < n) g_degi[i] = 0;
}

__global__ void k_conv_count(const void* eidx, int E) {
    int i = blockIdx.x * blockDim.x + threadIdx.x;
    if (i >= 2 * E) return;
    int v;
    if (g_is64) v = (int)((const long long*)eidx)[i];
    else        v = ((const int*)eidx)[i];
    if (i < E) {
        g_src[i] = v;
    } else {
        g_dst[i - E] = v;
        atomicAdd(&g_degi[v], 1);
    }
}

// ---------------- hierarchical exclusive scan of degrees ---------------------
__global__ void k_scan1(int n) {
    __shared__ int s[256];
    int i = blockIdx.x * 256 + threadIdx.x;
    int v = (i < n) ? g_degi[i] : 0;
    s[threadIdx.x] = v;
    __syncthreads();
    #pragma unroll
    for (int off = 1; off < 256; off <<= 1) {
        int t = (threadIdx.x >= off) ? s[threadIdx.x - off] : 0;
        __syncthreads();
        s[threadIdx.x] += t;
        __syncthreads();
    }
    if (i < n) g_offA[i] = s[threadIdx.x] - v;     // exclusive within block
    if (threadIdx.x == 255) g_bsum[blockIdx.x] = s[255];
}

__global__ void k_scan2(int nb) {                   // nb <= 1024
    __shared__ int s[1024];
    int v = (threadIdx.x < nb) ? g_bsum[threadIdx.x] : 0;
    s[threadIdx.x] = v;
    __syncthreads();
    #pragma unroll
    for (int off = 1; off < 1024; off <<= 1) {
        int t = (threadIdx.x >= off) ? s[threadIdx.x - off] : 0;
        __syncthreads();
        s[threadIdx.x] += t;
        __syncthreads();
    }
    if (threadIdx.x < nb) g_bpre[threadIdx.x] = s[threadIdx.x] - v;
}

__global__ void k_scan3(int n) {
    int i = blockIdx.x * blockDim.x + threadIdx.x;
    if (i >= n) return;
    int o = g_offA[i] + g_bpre[i >> 8];
    g_off[i]  = o;
    g_woff[i] = o;
    g_dis[i]  = rsqrtf((float)(g_degi[i] + 1));     // +1 self loop
}

// ---------------- counting-sort scatter: CSR of src by dst -------------------
__global__ void k_scatter(int E) {
    int e = blockIdx.x * blockDim.x + threadIdx.x;
    if (e >= E) return;
    int d = g_dst[e];
    int pos = atomicAdd(&g_woff[d], 1);
    g_csr[pos] = g_src[e];
}

// ---------------- GEMM1: h0 = x @ W1  (N x 128 @ 128 x 64) -------------------
__global__ __launch_bounds__(256) void k_gemm1(const float* __restrict__ x,
                                               const float* __restrict__ W,
                                               int n) {
    __shared__ float Ws[INC][HID];    // 32 KB
    __shared__ float xs[16][INC];     // 8 KB
    int tx = threadIdx.x, ty = threadIdx.y;          // blockDim (16,16)
    int tid = ty * 16 + tx;
    for (int i = tid; i < INC * HID; i += 256)
        ((float*)Ws)[i] = W[i];
    int row0 = blockIdx.x * 16;
    for (int i = tid; i < 16 * INC; i += 256) {
        int r = i >> 7, k = i & 127;
        int row = row0 + r;
        xs[r][k] = (row < n) ? x[row * INC + k] : 0.f;
    }
    __syncthreads();

    float4 acc = make_float4(0.f, 0.f, 0.f, 0.f);
    #pragma unroll 8
    for (int k = 0; k < INC; k++) {
        float xv = xs[ty][k];
        float4 w = *(const float4*)&Ws[k][tx * 4];
        acc.x += xv * w.x; acc.y += xv * w.y;
        acc.z += xv * w.z; acc.w += xv * w.w;
    }
    int row = row0 + ty;
    if (row < n) *(float4*)&g_h0[row * HID + tx * 4] = acc;
}

// ---------------- layer-1 pull aggregation (64ch, 16 thr/node) ---------------
// g_agg1[node] = relu( sum_{s in N(node)+self} h0[s]*dis[s]*dis[node] + b1 )
__global__ __launch_bounds__(256) void k_agg64(const float* __restrict__ b1,
                                               int n) {
    int tid  = threadIdx.x;
    int node = blockIdx.x * 16 + (tid >> 4);
    if (node >= n) return;
    int c4 = (tid & 15) << 2;
    float d  = g_dis[node];
    float dd = d * d;
    float4 v = *(const float4*)&g_h0[node * HID + c4];
    float4 acc = make_float4(v.x * dd, v.y * dd, v.z * dd, v.w * dd);

    int k   = g_off[node];
    int end = k + g_degi[node];
    for (; k + 1 < end; k += 2) {
        int s0 = g_csr[k], s1 = g_csr[k + 1];
        float n0 = g_dis[s0] * d;
        float n1 = g_dis[s1] * d;
        float4 a = *(const float4*)&g_h0[s0 * HID + c4];
        float4 b = *(const float4*)&g_h0[s1 * HID + c4];
        acc.x += a.x * n0 + b.x * n1;
        acc.y += a.y * n0 + b.y * n1;
        acc.z += a.z * n0 + b.z * n1;
        acc.w += a.w * n0 + b.w * n1;
    }
    if (k < end) {
        int s0 = g_csr[k];
        float n0 = g_dis[s0] * d;
        float4 a = *(const float4*)&g_h0[s0 * HID + c4];
        acc.x += a.x * n0; acc.y += a.y * n0;
        acc.z += a.z * n0; acc.w += a.w * n0;
    }
    float4 bb = *(const float4*)&b1[c4];
    acc.x = fmaxf(acc.x + bb.x, 0.f);
    acc.y = fmaxf(acc.y + bb.y, 0.f);
    acc.z = fmaxf(acc.z + bb.z, 0.f);
    acc.w = fmaxf(acc.w + bb.w, 0.f);
    *(float4*)&g_agg1[node * HID + c4] = acc;
}

// ---------------- GEMM2: z = agg1 @ [W_mu | W_ls] -----------------------------
__global__ __launch_bounds__(128) void k_gemm2(const float* __restrict__ Wmu,
                                               const float* __restrict__ Wls,
                                               int n) {
    __shared__ float Wc[HID][32];    // cols 0..15 = W_mu, 16..31 = W_ls
    __shared__ float hs[16][HID];
    int tx = threadIdx.x, ty = threadIdx.y;            // blockDim (8,16)
    int tid = ty * 8 + tx;
    for (int i = tid; i < HID * OUTC; i += 128) {
        int k = i >> 4, c = i & 15;
        Wc[k][c]      = Wmu[i];
        Wc[k][16 + c] = Wls[i];
    }
    int row0 = blockIdx.x * 16;
    for (int i = tid; i < 16 * HID; i += 128) {
        int r = i >> 6, k = i & 63;
        int row = row0 + r;
        hs[r][k] = (row < n) ? g_agg1[row * HID + k] : 0.f;
    }
    __syncthreads();

    float4 acc = make_float4(0.f, 0.f, 0.f, 0.f);
    #pragma unroll 8
    for (int k = 0; k < HID; k++) {
        float hv = hs[ty][k];
        float4 w = *(const float4*)&Wc[k][tx * 4];
        acc.x += hv * w.x; acc.y += hv * w.y;
        acc.z += hv * w.z; acc.w += hv * w.w;
    }
    int row = row0 + ty;
    if (row < n) *(float4*)&g_z[row * 32 + tx * 4] = acc;
}

// ---------------- layer-2 pull aggregation (32ch, 8 thr/node) ----------------
// out layout: [0 .. n*16) = mu, [n*16 .. n*32) = logstd
__global__ __launch_bounds__(256) void k_agg32(const float* __restrict__ bmu,
                                               const float* __restrict__ bls,
                                               float* __restrict__ out, int n) {
    int tid  = threadIdx.x;
    int node = blockIdx.x * 32 + (tid >> 3);
    if (node >= n) return;
    int c4 = (tid & 7) << 2;
    float d  = g_dis[node];
    float dd = d * d;
    float4 v = *(const float4*)&g_z[node * 32 + c4];
    float4 acc = make_float4(v.x * dd, v.y * dd, v.z * dd, v.w * dd);

    int k   = g_off[node];
    int end = k + g_degi[node];
    for (; k + 1 < end; k += 2) {
        int s0 = g_csr[k], s1 = g_csr[k + 1];
        float n0 = g_dis[s0] * d;
        float n1 = g_dis[s1] * d;
        float4 a = *(const float4*)&g_z[s0 * 32 + c4];
        float4 b = *(const float4*)&g_z[s1 * 32 + c4];
        acc.x += a.x * n0 + b.x * n1;
        acc.y += a.y * n0 + b.y * n1;
        acc.z += a.z * n0 + b.z * n1;
        acc.w += a.w * n0 + b.w * n1;
    }
    if (k < end) {
        int s0 = g_csr[k];
        float n0 = g_dis[s0] * d;
        float4 a = *(const float4*)&g_z[s0 * 32 + c4];
        acc.x += a.x * n0; acc.y += a.y * n0;
        acc.z += a.z * n0; acc.w += a.w * n0;
    }
    float4 bb;
    float* p;
    if (c4 < 16) {
        bb = *(const float4*)&bmu[c4];
        p = &out[node * 16 + c4];
    } else {
        bb = *(const float4*)&bls[c4 - 16];
        p = &out[n * 16 + node * 16 + (c4 - 16)];
    }
    acc.x += bb.x; acc.y += bb.y; acc.z += bb.z; acc.w += bb.w;
    *(float4*)p = acc;
}

// ---------------- launch ------------------------------------------------------
extern "C" void kernel_launch(void* const* d_in, const int* in_sizes, int n_in,
                              void* d_out, int out_size) {
    const float* x   = (const float*)d_in[0];
    const void*  eix = d_in[1];
    const float* W1  = (const float*)d_in[2];
    const float* b1  = (const float*)d_in[3];
    const float* Wmu = (const float*)d_in[4];
    const float* bmu = (const float*)d_in[5];
    const float* Wls = (const float*)d_in[6];
    const float* bls = (const float*)d_in[7];
    float* out = (float*)d_out;

    int n = in_sizes[0] / INC;      // 100000
    int E = in_sizes[1] / 2;        // 3200000
    int nb = (n + 255) / 256;       // scan blocks (<= 1024)

    k_detect<<<1, 1>>>((const int*)eix);
    k_zero_deg<<<nb, 256>>>(n);
    k_conv_count<<<(2 * E + 255) / 256, 256>>>(eix, E);

    k_scan1<<<nb, 256>>>(n);
    k_scan2<<<1, 1024>>>(nb);
    k_scan3<<<nb, 256>>>(n);
    k_scatter<<<(E + 255) / 256, 256>>>(E);

    k_gemm1<<<(n + 15) / 16, dim3(16, 16)>>>(x, W1, n);
    k_agg64<<<(n + 15) / 16, 256>>>(b1, n);

    k_gemm2<<<(n + 15) / 16, dim3(8, 16)>>>(Wmu, Wls, n);
    k_agg32<<<(n + 31) / 32, 256>>>(bmu, bls, out, n);
}

// round 5
// speedup vs baseline: 1.0106x; 1.0106x over previous
#include <cuda_runtime.h>
#include <cstdint>

// Problem constants (shapes fixed by the dataset)
#define NN   100000      // nodes
#define EE   3200000     // edges (without self loops)
#define INC  128
#define HID  64
#define OUTC 16

// ---------------- scratch (static device globals; no allocation) -------------
__device__ float g_h0[NN * HID];      // x @ W1
__device__ float g_agg1[NN * HID];    // relu(aggregated layer-1 + b1)
__device__ float g_z[NN * 32];        // agg1 @ [W_mu | W_ls]
__device__ float g_dis[NN];           // (deg+1)^-1/2
__device__ int   g_src[EE];
__device__ int   g_dst[EE];
__device__ int   g_csr[EE];           // src indices sorted by dst
__device__ int   g_degi[NN];          // edge in-degree (without self loop)
__device__ int   g_offA[NN];          // block-local exclusive scan
__device__ int   g_off[NN];           // global exclusive scan (CSR row ptr)
__device__ int   g_woff[NN];          // scatter write cursors
__device__ int   g_bsum[1024];
__device__ int   g_bpre[1024];
__device__ int   g_is64;

// ---------------- dtype detection + index conversion + degree count ----------
__global__ void k_detect(const int* e) {
    int all_zero = 1;
    #pragma unroll
    for (int i = 1; i < 129; i += 2)
        if (e[i] != 0) { all_zero = 0; break; }
    g_is64 = all_zero;
}

__global__ void k_zero_deg(int n) {
    int i = blockIdx.x * blockDim.x + threadIdx.x;
    if (i < n) g_degi[i] = 0;
}

__global__ void k_conv_count(const void* eidx, int E) {
    int i = blockIdx.x * blockDim.x + threadIdx.x;
    if (i >= 2 * E) return;
    int v;
    if (g_is64) v = (int)((const long long*)eidx)[i];
    else        v = ((const int*)eidx)[i];
    if (i < E) {
        g_src[i] = v;
    } else {
        g_dst[i - E] = v;
        atomicAdd(&g_degi[v], 1);
    }
}

// ---------------- hierarchical exclusive scan of degrees ---------------------
__global__ void k_scan1(int n) {
    __shared__ int s[256];
    int i = blockIdx.x * 256 + threadIdx.x;
    int v = (i < n) ? g_degi[i] : 0;
    s[threadIdx.x] = v;
    __syncthreads();
    #pragma unroll
    for (int off = 1; off < 256; off <<= 1) {
        int t = (threadIdx.x >= off) ? s[threadIdx.x - off] : 0;
        __syncthreads();
        s[threadIdx.x] += t;
        __syncthreads();
    }
    if (i < n) g_offA[i] = s[threadIdx.x] - v;     // exclusive within block
    if (threadIdx.x == 255) g_bsum[blockIdx.x] = s[255];
}

__global__ void k_scan2(int nb) {                   // nb <= 1024
    __shared__ int s[1024];
    int v = (threadIdx.x < nb) ? g_bsum[threadIdx.x] : 0;
    s[threadIdx.x] = v;
    __syncthreads();
    #pragma unroll
    for (int off = 1; off < 1024; off <<= 1) {
        int t = (threadIdx.x >= off) ? s[threadIdx.x - off] : 0;
        __syncthreads();
        s[threadIdx.x] += t;
        __syncthreads();
    }
    if (threadIdx.x < nb) g_bpre[threadIdx.x] = s[threadIdx.x] - v;
}

__global__ void k_scan3(int n) {
    int i = blockIdx.x * blockDim.x + threadIdx.x;
    if (i >= n) return;
    int o = g_offA[i] + g_bpre[i >> 8];
    g_off[i]  = o;
    g_woff[i] = o;
    g_dis[i]  = rsqrtf((float)(g_degi[i] + 1));     // +1 self loop
}

// ---------------- counting-sort scatter: CSR of src by dst -------------------
__global__ void k_scatter(int E) {
    int e = blockIdx.x * blockDim.x + threadIdx.x;
    if (e >= E) return;
    int d = g_dst[e];
    int pos = atomicAdd(&g_woff[d], 1);
    g_csr[pos] = g_src[e];
}

// ---------------- GEMM1: h0 = x @ W1  (N x 128 @ 128 x 64) -------------------
__global__ __launch_bounds__(256) void k_gemm1(const float* __restrict__ x,
                                               const float* __restrict__ W,
                                               int n) {
    __shared__ float Ws[INC][HID];    // 32 KB
    __shared__ float xs[16][INC];     // 8 KB
    int tx = threadIdx.x, ty = threadIdx.y;          // blockDim (16,16)
    int tid = ty * 16 + tx;
    for (int i = tid; i < INC * HID; i += 256)
        ((float*)Ws)[i] = W[i];
    int row0 = blockIdx.x * 16;
    for (int i = tid; i < 16 * INC; i += 256) {
        int r = i >> 7, k = i & 127;
        int row = row0 + r;
        xs[r][k] = (row < n) ? x[row * INC + k] : 0.f;
    }
    __syncthreads();

    float4 acc = make_float4(0.f, 0.f, 0.f, 0.f);
    #pragma unroll 8
    for (int k = 0; k < INC; k++) {
        float xv = xs[ty][k];
        float4 w = *(const float4*)&Ws[k][tx * 4];
        acc.x += xv * w.x; acc.y += xv * w.y;
        acc.z += xv * w.z; acc.w += xv * w.w;
    }
    int row = row0 + ty;
    if (row < n) *(float4*)&g_h0[row * HID + tx * 4] = acc;
}

// ---------------- layer-1 pull aggregation (64ch, 16 thr/node) ---------------
// g_agg1[node] = relu( sum_{s in N(node)+self} h0[s]*dis[s]*dis[node] + b1 )
__global__ __launch_bounds__(256) void k_agg64(const float* __restrict__ b1,
                                               int n) {
    int tid  = threadIdx.x;
    int node = blockIdx.x * 16 + (tid >> 4);
    if (node >= n) return;
    int c4 = (tid & 15) << 2;
    float d  = g_dis[node];
    float dd = d * d;
    float4 v = *(const float4*)&g_h0[node * HID + c4];
    float4 acc = make_float4(v.x * dd, v.y * dd, v.z * dd, v.w * dd);

    int k   = g_off[node];
    int end = k + g_degi[node];
    for (; k + 1 < end; k += 2) {
        int s0 = g_csr[k], s1 = g_csr[k + 1];
        float n0 = g_dis[s0] * d;
        float n1 = g_dis[s1] * d;
        float4 a = *(const float4*)&g_h0[s0 * HID + c4];
        float4 b = *(const float4*)&g_h0[s1 * HID + c4];
        acc.x += a.x * n0 + b.x * n1;
        acc.y += a.y * n0 + b.y * n1;
        acc.z += a.z * n0 + b.z * n1;
        acc.w += a.w * n0 + b.w * n1;
    }
    if (k < end) {
        int s0 = g_csr[k];
        float n0 = g_dis[s0] * d;
        float4 a = *(const float4*)&g_h0[s0 * HID + c4];
        acc.x += a.x * n0; acc.y += a.y * n0;
        acc.z += a.z * n0; acc.w += a.w * n0;
    }
    float4 bb = *(const float4*)&b1[c4];
    acc.x = fmaxf(acc.x + bb.x, 0.f);
    acc.y = fmaxf(acc.y + bb.y, 0.f);
    acc.z = fmaxf(acc.z + bb.z, 0.f);
    acc.w = fmaxf(acc.w + bb.w, 0.f);
    *(float4*)&g_agg1[node * HID + c4] = acc;
}

// ---------------- GEMM2: z = agg1 @ [W_mu | W_ls] -----------------------------
__global__ __launch_bounds__(128) void k_gemm2(const float* __restrict__ Wmu,
                                               const float* __restrict__ Wls,
                                               int n) {
    __shared__ float Wc[HID][32];    // cols 0..15 = W_mu, 16..31 = W_ls
    __shared__ float hs[16][HID];
    int tx = threadIdx.x, ty = threadIdx.y;            // blockDim (8,16)
    int tid = ty * 8 + tx;
    for (int i = tid; i < HID * OUTC; i += 128) {
        int k = i >> 4, c = i & 15;
        Wc[k][c]      = Wmu[i];
        Wc[k][16 + c] = Wls[i];
    }
    int row0 = blockIdx.x * 16;
    for (int i = tid; i < 16 * HID; i += 128) {
        int r = i >> 6, k = i & 63;
        int row = row0 + r;
        hs[r][k] = (row < n) ? g_agg1[row * HID + k] : 0.f;
    }
    __syncthreads();

    float4 acc = make_float4(0.f, 0.f, 0.f, 0.f);
    #pragma unroll 8
    for (int k = 0; k < HID; k++) {
        float hv = hs[ty][k];
        float4 w = *(const float4*)&Wc[k][tx * 4];
        acc.x += hv * w.x; acc.y += hv * w.y;
        acc.z += hv * w.z; acc.w += hv * w.w;
    }
    int row = row0 + ty;
    if (row < n) *(float4*)&g_z[row * 32 + tx * 4] = acc;
}

// ---------------- layer-2 pull aggregation (32ch, 8 thr/node) ----------------
// out layout: [0 .. n*16) = mu, [n*16 .. n*32) = logstd
__global__ __launch_bounds__(256) void k_agg32(const float* __restrict__ bmu,
                                               const float* __restrict__ bls,
                                               float* __restrict__ out, int n) {
    int tid  = threadIdx.x;
    int node = blockIdx.x * 32 + (tid >> 3);
    if (node >= n) return;
    int c4 = (tid & 7) << 2;
    float d  = g_dis[node];
    float dd = d * d;
    float4 v = *(const float4*)&g_z[node * 32 + c4];
    float4 acc = make_float4(v.x * dd, v.y * dd, v.z * dd, v.w * dd);

    int k   = g_off[node];
    int end = k + g_degi[node];
    for (; k + 1 < end; k += 2) {
        int s0 = g_csr[k], s1 = g_csr[k + 1];
        float n0 = g_dis[s0] * d;
        float n1 = g_dis[s1] * d;
        float4 a = *(const float4*)&g_z[s0 * 32 + c4];
        float4 b = *(const float4*)&g_z[s1 * 32 + c4];
        acc.x += a.x * n0 + b.x * n1;
        acc.y += a.y * n0 + b.y * n1;
        acc.z += a.z * n0 + b.z * n1;
        acc.w += a.w * n0 + b.w * n1;
    }
    if (k < end) {
        int s0 = g_csr[k];
        float n0 = g_dis[s0] * d;
        float4 a = *(const float4*)&g_z[s0 * 32 + c4];
        acc.x += a.x * n0; acc.y += a.y * n0;
        acc.z += a.z * n0; acc.w += a.w * n0;
    }
    float4 bb;
    float* p;
    if (c4 < 16) {
        bb = *(const float4*)&bmu[c4];
        p = &out[node * 16 + c4];
    } else {
        bb = *(const float4*)&bls[c4 - 16];
        p = &out[n * 16 + node * 16 + (c4 - 16)];
    }
    acc.x += bb.x; acc.y += bb.y; acc.z += bb.z; acc.w += bb.w;
    *(float4*)p = acc;
}

// ---------------- launch ------------------------------------------------------
extern "C" void kernel_launch(void* const* d_in, const int* in_sizes, int n_in,
                              void* d_out, int out_size) {
    const float* x   = (const float*)d_in[0];
    const void*  eix = d_in[1];
    const float* W1  = (const float*)d_in[2];
    const float* b1  = (const float*)d_in[3];
    const float* Wmu = (const float*)d_in[4];
    const float* bmu = (const float*)d_in[5];
    const float* Wls = (const float*)d_in[6];
    const float* bls = (const float*)d_in[7];
    float* out = (float*)d_out;

    int n = in_sizes[0] / INC;      // 100000
    int E = in_sizes[1] / 2;        // 3200000
    int nb = (n + 255) / 256;       // scan blocks (<= 1024)

    k_detect<<<1, 1>>>((const int*)eix);
    k_zero_deg<<<nb, 256>>>(n);
    k_conv_count<<<(2 * E + 255) / 256, 256>>>(eix, E);

    k_scan1<<<nb, 256>>>(n);
    k_scan2<<<1, 1024>>>(nb);
    k_scan3<<<nb, 256>>>(n);
    k_scatter<<<(E + 255) / 256, 256>>>(E);

    k_gemm1<<<(n + 15) / 16, dim3(16, 16)>>>(x, W1, n);
    k_agg64<<<(n + 15) / 16, 256>>>(b1, n);

    k_gemm2<<<(n + 15) / 16, dim3(8, 16)>>>(Wmu, Wls, n);
    k_agg32<<<(n + 31) / 32, 256>>>(bmu, bls, out, n);
}

// round 6
// speedup vs baseline: 1.0370x; 1.0261x over previous
#include <cuda_runtime.h>
#include <cstdint>

#define NN   100000
#define EE   3200000
#define INC  128
#define HID  64
#define OUTC 16

// ---------------- scratch (static device globals; no allocation) -------------
__device__ float g_h0[NN * HID];      // (x @ W1) * dis[row]   (pre-scaled)
__device__ float g_z[NN * 32];        // (relu(agg1) @ [Wmu|Wls]) * dis[row]
__device__ float g_dis[NN];           // (deg+1)^-1/2
__device__ int   g_src[EE];
__device__ int   g_dst[EE];
__device__ int   g_csr[EE];           // src indices sorted by dst
__device__ int   g_degi[NN];
__device__ int   g_offA[NN];
__device__ int   g_off[NN];
__device__ int   g_woff[NN];
__device__ int   g_bsum[1024];
__device__ int   g_bpre[1024];
__device__ int   g_is64;

// ---------------- dtype detection + index conversion + degree count ----------
__global__ void k_detect(const int* e) {
    int all_zero = 1;
    #pragma unroll
    for (int i = 1; i < 129; i += 2)
        if (e[i] != 0) { all_zero = 0; break; }
    g_is64 = all_zero;
}

__global__ void k_zero_deg(int n) {
    int i = blockIdx.x * blockDim.x + threadIdx.x;
    if (i < n) g_degi[i] = 0;
}

__global__ void k_conv_count(const void* eidx, int E) {
    int i = blockIdx.x * blockDim.x + threadIdx.x;
    if (i >= 2 * E) return;
    int v;
    if (g_is64) v = (int)((const long long*)eidx)[i];
    else        v = ((const int*)eidx)[i];
    if (i < E) {
        g_src[i] = v;
    } else {
        g_dst[i - E] = v;
        atomicAdd(&g_degi[v], 1);
    }
}

// ---------------- hierarchical exclusive scan of degrees ---------------------
__global__ void k_scan1(int n) {
    __shared__ int s[256];
    int i = blockIdx.x * 256 + threadIdx.x;
    int v = (i < n) ? g_degi[i] : 0;
    s[threadIdx.x] = v;
    __syncthreads();
    #pragma unroll
    for (int off = 1; off < 256; off <<= 1) {
        int t = (threadIdx.x >= off) ? s[threadIdx.x - off] : 0;
        __syncthreads();
        s[threadIdx.x] += t;
        __syncthreads();
    }
    if (i < n) g_offA[i] = s[threadIdx.x] - v;
    if (threadIdx.x == 255) g_bsum[blockIdx.x] = s[255];
}

__global__ void k_scan2(int nb) {
    __shared__ int s[1024];
    int v = (threadIdx.x < nb) ? g_bsum[threadIdx.x] : 0;
    s[threadIdx.x] = v;
    __syncthreads();
    #pragma unroll
    for (int off = 1; off < 1024; off <<= 1) {
        int t = (threadIdx.x >= off) ? s[threadIdx.x - off] : 0;
        __syncthreads();
        s[threadIdx.x] += t;
        __syncthreads();
    }
    if (threadIdx.x < nb) g_bpre[threadIdx.x] = s[threadIdx.x] - v;
}

__global__ void k_scan3(int n) {
    int i = blockIdx.x * blockDim.x + threadIdx.x;
    if (i >= n) return;
    int o = g_offA[i] + g_bpre[i >> 8];
    g_off[i]  = o;
    g_woff[i] = o;
    g_dis[i]  = rsqrtf((float)(g_degi[i] + 1));
}

// ---------------- counting-sort scatter: CSR of src by dst -------------------
__global__ void k_scatter(int E) {
    int e = blockIdx.x * blockDim.x + threadIdx.x;
    if (e >= E) return;
    int d = g_dst[e];
    int pos = atomicAdd(&g_woff[d], 1);
    g_csr[pos] = g_src[e];
}

// ---------------- GEMM1: h0 = (x @ W1) * dis[row] ----------------------------
__global__ __launch_bounds__(256) void k_gemm1(const float* __restrict__ x,
                                               const float* __restrict__ W,
                                               int n) {
    __shared__ float Ws[INC][HID];    // 32 KB
    __shared__ float xs[16][INC];     // 8 KB
    int tx = threadIdx.x, ty = threadIdx.y;          // blockDim (16,16)
    int tid = ty * 16 + tx;
    for (int i = tid; i < INC * HID; i += 256)
        ((float*)Ws)[i] = W[i];
    int row0 = blockIdx.x * 16;
    for (int i = tid; i < 16 * INC; i += 256) {
        int r = i >> 7, k = i & 127;
        int row = row0 + r;
        xs[r][k] = (row < n) ? x[row * INC + k] : 0.f;
    }
    __syncthreads();

    float4 acc = make_float4(0.f, 0.f, 0.f, 0.f);
    #pragma unroll 8
    for (int k = 0; k < INC; k++) {
        float xv = xs[ty][k];
        float4 w = *(const float4*)&Ws[k][tx * 4];
        acc.x += xv * w.x; acc.y += xv * w.y;
        acc.z += xv * w.z; acc.w += xv * w.w;
    }
    int row = row0 + ty;
    if (row < n) {
        float d = g_dis[row];                    // pre-scale by dis[src]
        acc.x *= d; acc.y *= d; acc.z *= d; acc.w *= d;
        *(float4*)&g_h0[row * HID + tx * 4] = acc;
    }
}

// ---------------- fused layer-1 aggregation + GEMM2 --------------------------
// One warp per node (32 thr, float2 = 64 ch). Then in-block 64x32 projection:
//   zs[node] = ( relu( dis[node]*(h0s[node] + sum h0s[src]) + b1 ) @ Wc ) * dis[node]
__global__ __launch_bounds__(256) void k_agg64_gemm2(const float* __restrict__ b1,
                                                     const float* __restrict__ Wmu,
                                                     const float* __restrict__ Wls,
                                                     int n) {
    __shared__ float hs[8][HID];     // 2 KB
    __shared__ float Wc[HID][32];    // 8 KB: cols 0..15 = W_mu, 16..31 = W_ls
    int tid  = threadIdx.x;
    int warp = tid >> 5, lane = tid & 31;
    for (int i = tid; i < HID * OUTC; i += 256) {
        int k = i >> 4, c = i & 15;
        Wc[k][c]      = Wmu[i];
        Wc[k][16 + c] = Wls[i];
    }
    int node = blockIdx.x * 8 + warp;
    if (node < n) {
        int c2 = lane * 2;
        float2 acc = *(const float2*)&g_h0[node * HID + c2];   // self (pre-scaled)
        int k   = g_off[node];
        int end = k + g_degi[node];
        for (; k + 3 < end; k += 4) {
            int s0 = g_csr[k],     s1 = g_csr[k + 1];
            int s2 = g_csr[k + 2], s3 = g_csr[k + 3];
            float2 a0 = *(const float2*)&g_h0[s0 * HID + c2];
            float2 a1 = *(const float2*)&g_h0[s1 * HID + c2];
            float2 a2 = *(const float2*)&g_h0[s2 * HID + c2];
            float2 a3 = *(const float2*)&g_h0[s3 * HID + c2];
            acc.x += a0.x + a1.x + a2.x + a3.x;
            acc.y += a0.y + a1.y + a2.y + a3.y;
        }
        for (; k < end; k++) {
            int s0 = g_csr[k];
            float2 a0 = *(const float2*)&g_h0[s0 * HID + c2];
            acc.x += a0.x; acc.y += a0.y;
        }
        float d = g_dis[node];
        float2 bb = *(const float2*)&b1[c2];
        hs[warp][c2]     = fmaxf(acc.x * d + bb.x, 0.f);
        hs[warp][c2 + 1] = fmaxf(acc.y * d + bb.y, 0.f);
    }
    __syncthreads();
    // projection: warp w computes 32 output cols of node (blockIdx*8 + w)
    if (node < n) {
        float sum = 0.f;
        #pragma unroll
        for (int k = 0; k < HID; k++)
            sum += hs[warp][k] * Wc[k][lane];
        g_z[node * 32 + lane] = sum * g_dis[node];             // pre-scale by dis
    }
}

// ---------------- layer-2 aggregation (one warp per node, 1 ch/thread) -------
// out layout: [0 .. n*16) = mu, [n*16 .. n*32) = logstd
__global__ __launch_bounds__(256) void k_agg32(const float* __restrict__ bmu,
                                               const float* __restrict__ bls,
                                               float* __restrict__ out, int n) {
    int tid  = threadIdx.x;
    int warp = tid >> 5, lane = tid & 31;
    int node = blockIdx.x * 8 + warp;
    if (node >= n) return;
    float acc = g_z[node * 32 + lane];                         // self (pre-scaled)
    int k   = g_off[node];
    int end = k + g_degi[node];
    for (; k + 3 < end; k += 4) {
        int s0 = g_csr[k],     s1 = g_csr[k + 1];
        int s2 = g_csr[k + 2], s3 = g_csr[k + 3];
        acc += g_z[s0 * 32 + lane] + g_z[s1 * 32 + lane]
             + g_z[s2 * 32 + lane] + g_z[s3 * 32 + lane];
    }
    for (; k < end; k++)
        acc += g_z[g_csr[k] * 32 + lane];
    float d = g_dis[node];
    if (lane < 16)
        out[node * 16 + lane] = acc * d + bmu[lane];
    else
        out[n * 16 + node * 16 + (lane - 16)] = acc * d + bls[lane - 16];
}

// ---------------- launch ------------------------------------------------------
extern "C" void kernel_launch(void* const* d_in, const int* in_sizes, int n_in,
                              void* d_out, int out_size) {
    const float* x   = (const float*)d_in[0];
    const void*  eix = d_in[1];
    const float* W1  = (const float*)d_in[2];
    const float* b1  = (const float*)d_in[3];
    const float* Wmu = (const float*)d_in[4];
    const float* bmu = (const float*)d_in[5];
    const float* Wls = (const float*)d_in[6];
    const float* bls = (const float*)d_in[7];
    float* out = (float*)d_out;

    int n = in_sizes[0] / INC;      // 100000
    int E = in_sizes[1] / 2;        // 3200000
    int nb = (n + 255) / 256;

    k_detect<<<1, 1>>>((const int*)eix);
    k_zero_deg<<<nb, 256>>>(n);
    k_conv_count<<<(2 * E + 255) / 256, 256>>>(eix, E);

    k_scan1<<<nb, 256>>>(n);
    k_scan2<<<1, 1024>>>(nb);
    k_scan3<<<nb, 256>>>(n);
    k_scatter<<<(E + 255) / 256, 256>>>(E);

    k_gemm1<<<(n + 15) / 16, dim3(16, 16)>>>(x, W1, n);
    k_agg64_gemm2<<<(n + 7) / 8, 256>>>(b1, Wmu, Wls, n);
    k_agg32<<<(n + 7) / 8, 256>>>(bmu, bls, out, n);
}